// round 13
// baseline (speedup 1.0000x reference)
#include <cuda_runtime.h>
#include <cstdint>

// YOLOv1 loss: preds [N,7,7,30] f32, labels [N,7,7,30] f32 -> scalar f32.
// R13: deep-ring design. 1 CTA/SM (grid=148), 256 threads, TILE=256 cells,
// 3-stage ring in 184KB dynamic smem, wait_group 2 => TWO full stages
// (123KB/SM) in flight through the compute+barrier phase. Fused reduction.

#define TILE_CELLS 256
#define THREADS 256
#define FLOATS_PER_CELL 30
#define F4_PER_ARRAY 1920           // 256*30/4
#define F4_PER_TILE 3840            // preds + labels
#define ITERS_PER_STAGE 15          // 3840 / 256 threads
#define STAGES 3
#define N_BLOCKS 148                // one CTA per SM, single wave
#define SMEM_BYTES (STAGES * F4_PER_TILE * 16)   // 184320

__device__ float g_partials[N_BLOCKS];
__device__ unsigned int g_count;    // zero-init; atomicInc wraps to 0 -> replay-safe

__device__ __forceinline__ uint32_t smem_addr_u32(const void* p) {
    return (uint32_t)__cvta_generic_to_shared(p);
}

#define CP_ASYNC16(dst_u32, src_ptr) \
    asm volatile("cp.async.cg.shared.global [%0], [%1], 16;\n" :: "r"(dst_u32), "l"(src_ptr))
#define CP_COMMIT() asm volatile("cp.async.commit_group;\n" ::)
#define CP_WAIT2()  asm volatile("cp.async.wait_group 2;\n" ::)

__device__ __forceinline__ float rcp_approx(float x) {
    float y; asm("rcp.approx.f32 %0, %1;" : "=f"(y) : "f"(x)); return y;
}
__device__ __forceinline__ float sqrt_approx(float x) {
    float y; asm("sqrt.approx.f32 %0, %1;" : "=f"(y) : "f"(x)); return y;
}

// inter & union of (cx,cy,w,h) boxes; no division here.
__device__ __forceinline__ void iou_parts(const float* a, const float* b,
                                          float& inter, float& uni) {
    float ax1 = a[0] - a[2] * 0.5f, ay1 = a[1] - a[3] * 0.5f;
    float ax2 = a[0] + a[2] * 0.5f, ay2 = a[1] + a[3] * 0.5f;
    float bx1 = b[0] - b[2] * 0.5f, by1 = b[1] - b[3] * 0.5f;
    float bx2 = b[0] + b[2] * 0.5f, by2 = b[1] + b[3] * 0.5f;
    float iw = fmaxf(fminf(ax2, bx2) - fmaxf(ax1, bx1), 0.0f);
    float ih = fmaxf(fminf(ay2, by2) - fmaxf(ay1, by1), 0.0f);
    inter = iw * ih;
    uni = a[2] * a[3] + b[2] * b[3] - inter + 1e-10f;
}

__global__ __launch_bounds__(THREADS) void yolo_loss_ring_kernel(
    const float4* __restrict__ preds4,
    const float4* __restrict__ labels4,
    float* __restrict__ out,
    int n_tiles, float inv_batch)
{
    extern __shared__ float4 ring[];          // [STAGES][F4_PER_TILE]
    __shared__ float warp_s[THREADS / 32];
    __shared__ bool is_last;

    const int tid = threadIdx.x;
    const int g = gridDim.x;

    // Issue one tile's loads into stage s. Tiling is exact (802816%256==0),
    // so no tail predicates. Always commits a group (possibly empty) so
    // wait_group counting stays exact past the end.
    auto issue_tile = [&](int t, int s) {
        if (t < n_tiles) {
            const int base = t * F4_PER_ARRAY;
            float4* stage = ring + s * F4_PER_TILE;
#pragma unroll
            for (int k = 0; k < ITERS_PER_STAGE; ++k) {
                const int i = tid + k * THREADS;           // 0..3839
                const bool is_p = (i < F4_PER_ARRAY);
                const int j = is_p ? i : (i - F4_PER_ARRAY);
                const float4* src = (is_p ? preds4 : labels4) + base + j;
                CP_ASYNC16(smem_addr_u32(stage + i), src);
            }
        }
        CP_COMMIT();
    };

    float loss = 0.0f;
    const int t0 = blockIdx.x;

    // Prologue: two tiles already in flight.
    issue_tile(t0,     0);
    issue_tile(t0 + g, 1);

    int s = 0;
    for (int t = t0; t < n_tiles; t += g) {
        // Refill the stage that finished computing 2 iterations ago; the
        // end-of-loop barrier below ordered that compute before this issue.
        issue_tile(t + 2 * g, (s + 2 >= STAGES) ? s + 2 - STAGES : s + 2);
        CP_WAIT2();          // oldest group (stage s) landed; 2 stages still flying
        __syncthreads();     // all threads' copies of stage s visible to all

        {
            const float* bp = (const float*)(ring + s * F4_PER_TILE);
            const float* p = bp + tid * FLOATS_PER_CELL;
            const float* l = bp + 4 * F4_PER_ARRAY + tid * FLOATS_PER_CELL;

            const float obj = (l[4] == 1.0f) ? 1.0f : 0.0f;

            // Both IoUs with one reciprocal.
            float n1, u1, n2, u2;
            iou_parts(p, l, n1, u1);
            iou_parts(p + 5, l, n2, u2);
            const float r = rcp_approx(u1 * u2);
            const float i1 = n1 * u2 * r;
            const float i2 = n2 * u1 * r;
            const bool b1 = i1 > i2;

            const float* pr = b1 ? p : (p + 5);
            const float* po = b1 ? (p + 5) : p;
            const float* lr = b1 ? l : (l + 5);   // label box duplicated in data
            const float iou_r = b1 ? i1 : i2;
            const float iou_o = b1 ? i2 : i1;

            float dx = pr[0] - lr[0];
            float dy = pr[1] - lr[1];
            float d_xy = dx * dx + dy * dy;

            // (sqrt(a)-sqrt(b))^2 = a + b - 2*sqrt(ab)
            const float pw = pr[2], ph = pr[3], lw = lr[2], lh = lr[3];
            float d_wh = (pw + lw - 2.0f * sqrt_approx(pw * lw))
                       + (ph + lh - 2.0f * sqrt_approx(ph * lh));

            float d_obj = pr[4] - iou_r;  d_obj *= d_obj;
            float d_no  = po[4] - iou_o;  d_no  *= d_no;
            float d_out = p[4] * p[4] + p[9] * p[9];

            float d_cls = 0.0f;
#pragma unroll
            for (int c = 10; c < 30; ++c) {
                float d = p[c] - l[c];
                d_cls = fmaf(d, d, d_cls);
            }

            loss += obj * (5.0f * d_xy + d_wh + d_obj + 0.5f * d_no + d_cls)
                  + (1.0f - obj) * 0.5f * d_out;
        }

        __syncthreads();     // all done with stage s before it can be refilled
        s = (s + 1 >= STAGES) ? 0 : s + 1;
    }

    // Per-block reduction -> partials slot.
#pragma unroll
    for (int o = 16; o > 0; o >>= 1)
        loss += __shfl_xor_sync(0xffffffffu, loss, o);
    if ((tid & 31) == 0) warp_s[tid >> 5] = loss;
    __syncthreads();

    if (tid == 0) {
        float bsum = 0.0f;
#pragma unroll
        for (int w = 0; w < THREADS / 32; ++w) bsum += warp_s[w];
        g_partials[blockIdx.x] = bsum;
        __threadfence();
        unsigned int v = atomicInc(&g_count, gridDim.x - 1);  // wraps to 0 on last
        is_last = (v == gridDim.x - 1);
    }
    __syncthreads();

    // Last-arriving block folds all partials and writes the scalar output.
    if (is_last) {
        float tsum = 0.0f;
        for (int i = tid; i < (int)gridDim.x; i += THREADS)
            tsum += g_partials[i];
#pragma unroll
        for (int o = 16; o > 0; o >>= 1)
            tsum += __shfl_xor_sync(0xffffffffu, tsum, o);
        if ((tid & 31) == 0) warp_s[tid >> 5] = tsum;
        __syncthreads();
        if (tid == 0) {
            float fsum = 0.0f;
#pragma unroll
            for (int w = 0; w < THREADS / 32; ++w) fsum += warp_s[w];
            out[0] = fsum * inv_batch;
        }
    }
}

extern "C" void kernel_launch(void* const* d_in, const int* in_sizes, int n_in,
                              void* d_out, int out_size)
{
    const float4* preds4  = (const float4*)d_in[0];
    const float4* labels4 = (const float4*)d_in[1];
    float* out = (float*)d_out;

    const int total_floats = in_sizes[0];                    // N*7*7*30
    const int n_cells = total_floats / FLOATS_PER_CELL;      // N*49
    const int batch = n_cells / 49;                          // N
    const int n_tiles = n_cells / TILE_CELLS;                // exact: 802816/256 = 3136

    static bool attr_set = false;
    if (!attr_set) {
        cudaFuncSetAttribute(yolo_loss_ring_kernel,
                             cudaFuncAttributeMaxDynamicSharedMemorySize,
                             SMEM_BYTES);
        attr_set = true;
    }

    yolo_loss_ring_kernel<<<N_BLOCKS, THREADS, SMEM_BYTES>>>(
        preds4, labels4, out, n_tiles, 1.0f / (float)batch);
}

// round 16
// speedup vs baseline: 1.1360x; 1.1360x over previous
#include <cuda_runtime.h>
#include <cstdint>

// YOLOv1 loss: preds [N,7,7,30] f32, labels [N,7,7,30] f32 -> scalar f32.
// R15 (= R14 re-run after infra failure). Best-regime consolidation:
// 12 warps/SM in 3 barrier domains: TILE=128, THREADS=128, 2-stage cp.async
// (60KB dynamic smem, 3 CTAs/SM), exact tiling (no predicates),
// issue-before-wait, MUFU-light math, fused single-launch final reduction.

#define TILE_CELLS 128
#define THREADS 128
#define FLOATS_PER_CELL 30
#define F4_PER_ARRAY 960            // 128*30/4
#define F4_PER_TILE 1920            // preds + labels
#define ITERS_PER_STAGE 15          // 1920 / 128 threads
#define MAX_BLOCKS 444              // 3 CTAs/SM * 148 SMs
#define SMEM_BYTES (2 * F4_PER_TILE * 16)   // 61440

__device__ float g_partials[MAX_BLOCKS];
__device__ unsigned int g_count;    // zero-init; atomicInc wraps to 0 -> replay-safe

__device__ __forceinline__ uint32_t smem_addr_u32(const void* p) {
    return (uint32_t)__cvta_generic_to_shared(p);
}

#define CP_ASYNC16(dst_u32, src_ptr) \
    asm volatile("cp.async.cg.shared.global [%0], [%1], 16;\n" :: "r"(dst_u32), "l"(src_ptr))
#define CP_COMMIT() asm volatile("cp.async.commit_group;\n" ::)
#define CP_WAIT1()  asm volatile("cp.async.wait_group 1;\n" ::)

__device__ __forceinline__ float rcp_approx(float x) {
    float y; asm("rcp.approx.f32 %0, %1;" : "=f"(y) : "f"(x)); return y;
}
__device__ __forceinline__ float sqrt_approx(float x) {
    float y; asm("sqrt.approx.f32 %0, %1;" : "=f"(y) : "f"(x)); return y;
}

// inter & union of (cx,cy,w,h) boxes; no division here.
__device__ __forceinline__ void iou_parts(const float* a, const float* b,
                                          float& inter, float& uni) {
    float ax1 = a[0] - a[2] * 0.5f, ay1 = a[1] - a[3] * 0.5f;
    float ax2 = a[0] + a[2] * 0.5f, ay2 = a[1] + a[3] * 0.5f;
    float bx1 = b[0] - b[2] * 0.5f, by1 = b[1] - b[3] * 0.5f;
    float bx2 = b[0] + b[2] * 0.5f, by2 = b[1] + b[3] * 0.5f;
    float iw = fmaxf(fminf(ax2, bx2) - fmaxf(ax1, bx1), 0.0f);
    float ih = fmaxf(fminf(ay2, by2) - fmaxf(ay1, by1), 0.0f);
    inter = iw * ih;
    uni = a[2] * a[3] + b[2] * b[3] - inter + 1e-10f;
}

__global__ __launch_bounds__(THREADS) void yolo_loss_t128_kernel(
    const float4* __restrict__ preds4,
    const float4* __restrict__ labels4,
    float* __restrict__ out,
    int n_tiles, float inv_batch)
{
    extern __shared__ float4 buf[];          // [2][F4_PER_TILE]
    __shared__ float warp_s[THREADS / 32];
    __shared__ bool is_last;

    const int tid = threadIdx.x;

    // Exact tiling: no tail predicates anywhere. Always commit a (possibly
    // empty) group so wait_group counting stays exact past the end.
    auto issue_tile = [&](int t, int s) {
        if (t < n_tiles) {
            const int base = t * F4_PER_ARRAY;
            float4* stage = buf + s * F4_PER_TILE;
#pragma unroll
            for (int k = 0; k < ITERS_PER_STAGE; ++k) {
                const int i = tid + k * THREADS;           // 0..1919
                const bool is_p = (i < F4_PER_ARRAY);
                const int j = is_p ? i : (i - F4_PER_ARRAY);
                const float4* src = (is_p ? preds4 : labels4) + base + j;
                CP_ASYNC16(smem_addr_u32(stage + i), src);
            }
        }
        CP_COMMIT();
    };

    float loss = 0.0f;
    int s = 0;

    // Prologue: prefetch first tile.
    issue_tile((int)blockIdx.x, 0);

    for (int t = blockIdx.x; t < n_tiles; t += gridDim.x) {
        issue_tile(t + gridDim.x, s ^ 1);   // next tile stays in flight
        CP_WAIT1();                          // stage s landed (s^1 still flying)
        __syncthreads();

        {
            const float* bp = (const float*)(buf + s * F4_PER_TILE);
            const float* p = bp + tid * FLOATS_PER_CELL;
            const float* l = bp + 4 * F4_PER_ARRAY + tid * FLOATS_PER_CELL;

            const float obj = (l[4] == 1.0f) ? 1.0f : 0.0f;

            // Both IoUs with one reciprocal:
            // r = 1/(u1*u2); i1 = n1*u2*r; i2 = n2*u1*r.
            float n1, u1, n2, u2;
            iou_parts(p, l, n1, u1);
            iou_parts(p + 5, l, n2, u2);
            const float r = rcp_approx(u1 * u2);
            const float i1 = n1 * u2 * r;
            const float i2 = n2 * u1 * r;
            const bool b1 = i1 > i2;

            const float* pr = b1 ? p : (p + 5);
            const float* po = b1 ? (p + 5) : p;
            const float* lr = b1 ? l : (l + 5);   // label box duplicated in data
            const float iou_r = b1 ? i1 : i2;
            const float iou_o = b1 ? i2 : i1;

            float dx = pr[0] - lr[0];
            float dy = pr[1] - lr[1];
            float d_xy = dx * dx + dy * dy;

            // (sqrt(a)-sqrt(b))^2 = a + b - 2*sqrt(ab): 2 MUFU instead of 4.
            const float pw = pr[2], ph = pr[3], lw = lr[2], lh = lr[3];
            float d_wh = (pw + lw - 2.0f * sqrt_approx(pw * lw))
                       + (ph + lh - 2.0f * sqrt_approx(ph * lh));

            float d_obj = pr[4] - iou_r;  d_obj *= d_obj;
            float d_no  = po[4] - iou_o;  d_no  *= d_no;
            float d_out = p[4] * p[4] + p[9] * p[9];

            float d_cls = 0.0f;
#pragma unroll
            for (int c = 10; c < 30; ++c) {
                float d = p[c] - l[c];
                d_cls = fmaf(d, d, d_cls);
            }

            loss += obj * (5.0f * d_xy + d_wh + d_obj + 0.5f * d_no + d_cls)
                  + (1.0f - obj) * 0.5f * d_out;
        }

        __syncthreads();            // everyone done with stage s before refill
        s ^= 1;
    }

    // Per-block reduction -> partials slot.
#pragma unroll
    for (int o = 16; o > 0; o >>= 1)
        loss += __shfl_xor_sync(0xffffffffu, loss, o);
    if ((tid & 31) == 0) warp_s[tid >> 5] = loss;
    __syncthreads();

    if (tid == 0) {
        g_partials[blockIdx.x] = warp_s[0] + warp_s[1] + warp_s[2] + warp_s[3];
        __threadfence();
        unsigned int v = atomicInc(&g_count, gridDim.x - 1);  // wraps to 0 on last
        is_last = (v == gridDim.x - 1);
    }
    __syncthreads();

    // Last-arriving block folds all partials and writes the scalar output.
    if (is_last) {
        float tsum = 0.0f;
        for (int i = tid; i < (int)gridDim.x; i += THREADS)
            tsum += g_partials[i];
#pragma unroll
        for (int o = 16; o > 0; o >>= 1)
            tsum += __shfl_xor_sync(0xffffffffu, tsum, o);
        if ((tid & 31) == 0) warp_s[tid >> 5] = tsum;
        __syncthreads();
        if (tid == 0)
            out[0] = (warp_s[0] + warp_s[1] + warp_s[2] + warp_s[3]) * inv_batch;
    }
}

extern "C" void kernel_launch(void* const* d_in, const int* in_sizes, int n_in,
                              void* d_out, int out_size)
{
    const float4* preds4  = (const float4*)d_in[0];
    const float4* labels4 = (const float4*)d_in[1];
    float* out = (float*)d_out;

    const int total_floats = in_sizes[0];                    // N*7*7*30
    const int n_cells = total_floats / FLOATS_PER_CELL;      // N*49
    const int batch = n_cells / 49;                          // N
    const int n_tiles = n_cells / TILE_CELLS;                // exact: 802816/128 = 6272

    // Idempotent, deterministic host-side call every launch (no static guard).
    cudaFuncSetAttribute(yolo_loss_t128_kernel,
                         cudaFuncAttributeMaxDynamicSharedMemorySize,
                         SMEM_BYTES);

    const int n_blocks = (n_tiles < MAX_BLOCKS) ? n_tiles : MAX_BLOCKS;
    yolo_loss_t128_kernel<<<n_blocks, THREADS, SMEM_BYTES>>>(
        preds4, labels4, out, n_tiles, 1.0f / (float)batch);
}

// round 17
// speedup vs baseline: 1.1474x; 1.0101x over previous
#include <cuda_runtime.h>
#include <cstdint>

// YOLOv1 loss: preds [N,7,7,30] f32, labels [N,7,7,30] f32 -> scalar f32.
// R17: bulk-TMA staging. Per tile: TWO cp.async.bulk (one per stream) issued by
// one thread, completing on an mbarrier (expect_tx) -- replaces 1920 per-thread
// cp.async, freeing all per-warp LSU issue slots + L1tex wavefronts for the
// LDS consumption side. TILE=128, THREADS=128, 2 stages, 3 CTAs/SM,
// one __syncthreads per tile, MUFU-light math, fused final reduction.

#define TILE_CELLS 128
#define THREADS 128
#define FLOATS_PER_CELL 30
#define F4_PER_ARRAY 960                     // 128*30/4
#define F4_PER_TILE 1920                     // preds + labels
#define STAGE_BYTES_PER_ARRAY 15360          // 960 * 16
#define STAGE_BYTES 30720                    // both arrays
#define MAX_BLOCKS 444                       // 3 CTAs/SM * 148 SMs
#define SMEM_BYTES (2 * F4_PER_TILE * 16)    // 61440 dynamic

__device__ float g_partials[MAX_BLOCKS];
__device__ unsigned int g_count;             // zero-init; atomicInc wraps -> replay-safe

__device__ __forceinline__ uint32_t smem_u32(const void* p) {
    return (uint32_t)__cvta_generic_to_shared(p);
}

__device__ __forceinline__ void mbar_init(uint32_t mbar, uint32_t count) {
    asm volatile("mbarrier.init.shared.b64 [%0], %1;" :: "r"(mbar), "r"(count) : "memory");
}
__device__ __forceinline__ void mbar_expect_tx(uint32_t mbar, uint32_t bytes) {
    asm volatile("mbarrier.arrive.expect_tx.shared.b64 _, [%0], %1;"
                 :: "r"(mbar), "r"(bytes) : "memory");
}
__device__ __forceinline__ void mbar_wait_parity(uint32_t mbar, uint32_t phase) {
    uint32_t done;
    asm volatile(
        "{\n\t.reg .pred p;\n\t"
        "mbarrier.try_wait.parity.acquire.cta.shared::cta.b64 p, [%1], %2;\n\t"
        "selp.b32 %0, 1, 0, p;\n\t}"
        : "=r"(done) : "r"(mbar), "r"(phase) : "memory");
    if (!done) {
        asm volatile(
            "{\n\t.reg .pred P1;\n\t"
            "WAIT_LOOP_%=:\n\t"
            "mbarrier.try_wait.parity.acquire.cta.shared::cta.b64 P1, [%0], %1, 0x989680;\n\t"
            "@P1 bra.uni WAIT_DONE_%=;\n\t"
            "bra.uni WAIT_LOOP_%=;\n\t"
            "WAIT_DONE_%=:\n\t}"
            :: "r"(mbar), "r"(phase) : "memory");
    }
}
__device__ __forceinline__ void bulk_g2s(uint32_t dst_smem, const void* src,
                                         uint32_t bytes, uint32_t mbar) {
    asm volatile(
        "cp.async.bulk.shared::cta.global.mbarrier::complete_tx::bytes [%0], [%1], %2, [%3];"
        :: "r"(dst_smem), "l"(src), "r"(bytes), "r"(mbar) : "memory");
}

__device__ __forceinline__ float rcp_approx(float x) {
    float y; asm("rcp.approx.f32 %0, %1;" : "=f"(y) : "f"(x)); return y;
}
__device__ __forceinline__ float sqrt_approx(float x) {
    float y; asm("sqrt.approx.f32 %0, %1;" : "=f"(y) : "f"(x)); return y;
}

// inter & union of (cx,cy,w,h) boxes; no division here.
__device__ __forceinline__ void iou_parts(const float* a, const float* b,
                                          float& inter, float& uni) {
    float ax1 = a[0] - a[2] * 0.5f, ay1 = a[1] - a[3] * 0.5f;
    float ax2 = a[0] + a[2] * 0.5f, ay2 = a[1] + a[3] * 0.5f;
    float bx1 = b[0] - b[2] * 0.5f, by1 = b[1] - b[3] * 0.5f;
    float bx2 = b[0] + b[2] * 0.5f, by2 = b[1] + b[3] * 0.5f;
    float iw = fmaxf(fminf(ax2, bx2) - fmaxf(ax1, bx1), 0.0f);
    float ih = fmaxf(fminf(ay2, by2) - fmaxf(ay1, by1), 0.0f);
    inter = iw * ih;
    uni = a[2] * a[3] + b[2] * b[3] - inter + 1e-10f;
}

__global__ __launch_bounds__(THREADS) void yolo_loss_tma_kernel(
    const char* __restrict__ predsB,
    const char* __restrict__ labelsB,
    float* __restrict__ out,
    int n_tiles, float inv_batch)
{
    extern __shared__ float4 buf[];          // [2][F4_PER_TILE]: preds | labels
    __shared__ __align__(8) uint64_t mbar[2];
    __shared__ float warp_s[THREADS / 32];
    __shared__ bool is_last;

    const int tid = threadIdx.x;
    const int g = gridDim.x;
    const uint32_t mb0 = smem_u32(&mbar[0]);
    const uint32_t mb1 = smem_u32(&mbar[1]);

    if (tid == 0) {
        mbar_init(mb0, 1);
        mbar_init(mb1, 1);
        // Make mbarrier init visible to the async proxy before first TMA.
        asm volatile("fence.proxy.async.shared::cta;" ::: "memory");
    }
    __syncthreads();

    // Single-thread bulk issue of one tile into stage s.
    auto issue_tile = [&](int t, int s) {
        if (tid == 0 && t < n_tiles) {
            const uint32_t mb = s ? mb1 : mb0;
            const uint32_t dst = smem_u32(buf + s * F4_PER_TILE);
            mbar_expect_tx(mb, STAGE_BYTES);
            bulk_g2s(dst, predsB + (size_t)t * STAGE_BYTES_PER_ARRAY,
                     STAGE_BYTES_PER_ARRAY, mb);
            bulk_g2s(dst + STAGE_BYTES_PER_ARRAY,
                     labelsB + (size_t)t * STAGE_BYTES_PER_ARRAY,
                     STAGE_BYTES_PER_ARRAY, mb);
        }
    };

    float loss = 0.0f;
    uint32_t ph0 = 0, ph1 = 0;               // per-stage phase parity
    int s = 0;

    // Prologue: first tile in flight.
    issue_tile((int)blockIdx.x, 0);

    for (int t = blockIdx.x; t < n_tiles; t += g) {
        // Refill the other stage (computed last iteration, ordered by the
        // barrier at the end of that iteration).
        issue_tile(t + g, s ^ 1);

        // Wait for stage s data (TMA complete_tx flips the barrier).
        if (s == 0) { mbar_wait_parity(mb0, ph0); ph0 ^= 1; }
        else        { mbar_wait_parity(mb1, ph1); ph1 ^= 1; }

        {
            const float* bp = (const float*)(buf + s * F4_PER_TILE);
            const float* p = bp + tid * FLOATS_PER_CELL;
            const float* l = bp + 4 * F4_PER_ARRAY + tid * FLOATS_PER_CELL;

            const float obj = (l[4] == 1.0f) ? 1.0f : 0.0f;

            // Both IoUs with one reciprocal.
            float n1, u1, n2, u2;
            iou_parts(p, l, n1, u1);
            iou_parts(p + 5, l, n2, u2);
            const float r = rcp_approx(u1 * u2);
            const float i1 = n1 * u2 * r;
            const float i2 = n2 * u1 * r;
            const bool b1 = i1 > i2;

            const float* pr = b1 ? p : (p + 5);
            const float* po = b1 ? (p + 5) : p;
            const float* lr = b1 ? l : (l + 5);   // label box duplicated in data
            const float iou_r = b1 ? i1 : i2;
            const float iou_o = b1 ? i2 : i1;

            float dx = pr[0] - lr[0];
            float dy = pr[1] - lr[1];
            float d_xy = dx * dx + dy * dy;

            // (sqrt(a)-sqrt(b))^2 = a + b - 2*sqrt(ab).
            const float pw = pr[2], ph = pr[3], lw = lr[2], lh = lr[3];
            float d_wh = (pw + lw - 2.0f * sqrt_approx(pw * lw))
                       + (ph + lh - 2.0f * sqrt_approx(ph * lh));

            float d_obj = pr[4] - iou_r;  d_obj *= d_obj;
            float d_no  = po[4] - iou_o;  d_no  *= d_no;
            float d_out = p[4] * p[4] + p[9] * p[9];

            float d_cls = 0.0f;
#pragma unroll
            for (int c = 10; c < 30; ++c) {
                float d = p[c] - l[c];
                d_cls = fmaf(d, d, d_cls);
            }

            loss += obj * (5.0f * d_xy + d_wh + d_obj + 0.5f * d_no + d_cls)
                  + (1.0f - obj) * 0.5f * d_out;
        }

        // All threads done with stage s before next iteration refills it.
        __syncthreads();
        s ^= 1;
    }

    // Per-block reduction -> partials slot.
#pragma unroll
    for (int o = 16; o > 0; o >>= 1)
        loss += __shfl_xor_sync(0xffffffffu, loss, o);
    if ((tid & 31) == 0) warp_s[tid >> 5] = loss;
    __syncthreads();

    if (tid == 0) {
        g_partials[blockIdx.x] = warp_s[0] + warp_s[1] + warp_s[2] + warp_s[3];
        __threadfence();
        unsigned int v = atomicInc(&g_count, gridDim.x - 1);  // wraps to 0 on last
        is_last = (v == gridDim.x - 1);
    }
    __syncthreads();

    // Last-arriving block folds all partials and writes the scalar output.
    if (is_last) {
        float tsum = 0.0f;
        for (int i = tid; i < (int)gridDim.x; i += THREADS)
            tsum += g_partials[i];
#pragma unroll
        for (int o = 16; o > 0; o >>= 1)
            tsum += __shfl_xor_sync(0xffffffffu, tsum, o);
        if ((tid & 31) == 0) warp_s[tid >> 5] = tsum;
        __syncthreads();
        if (tid == 0)
            out[0] = (warp_s[0] + warp_s[1] + warp_s[2] + warp_s[3]) * inv_batch;
    }
}

extern "C" void kernel_launch(void* const* d_in, const int* in_sizes, int n_in,
                              void* d_out, int out_size)
{
    const char* predsB  = (const char*)d_in[0];
    const char* labelsB = (const char*)d_in[1];
    float* out = (float*)d_out;

    const int total_floats = in_sizes[0];                    // N*7*7*30
    const int n_cells = total_floats / FLOATS_PER_CELL;      // N*49
    const int batch = n_cells / 49;                          // N
    const int n_tiles = n_cells / TILE_CELLS;                // exact: 802816/128 = 6272

    // Idempotent, deterministic host-side call every launch.
    cudaFuncSetAttribute(yolo_loss_tma_kernel,
                         cudaFuncAttributeMaxDynamicSharedMemorySize,
                         SMEM_BYTES);

    const int n_blocks = (n_tiles < MAX_BLOCKS) ? n_tiles : MAX_BLOCKS;
    yolo_loss_tma_kernel<<<n_blocks, THREADS, SMEM_BYTES>>>(
        predsB, labelsB, out, n_tiles, 1.0f / (float)batch);
}